// round 13
// baseline (speedup 1.0000x reference)
#include <cuda_runtime.h>
#include <cstdint>

// Problem constants (from reference):
//   x: [B=64, E=2048] int32, values in [1, 2047]
//   Y: [J=2048, E=2048, B=64] float32
//   Y[j,e,b] = ((2*x[b,j]+1) >> min(E-1-e, 31)) & 1
// v = 2*x+1 <= 4095 < 2^12  =>  bit is 0 for all e < E-13 = 2035.
// Only the last 13 e-columns per j are nonzero (~0.64% of 1.07 GB).
//
// Session history (all measured on sm_103a):
//   R3  flat 2x/thr (split halves):     145.8us, DRAM 89.3%
//   R4  flat 4x/thr (split quarters):   145.5us, DRAM 89.2%  <- BEST
//   R7  persistent 1-wave grid-stride:  174.1us, DRAM 75.0%  (worse)
//   R9  R4 confirm:                     145.6us, DRAM 89.5%
//   R10 128-thread blocks:              145.5us, DRAM 89.1%  (neutral)
//   R11 per-thread-contiguous 4x:       244.2us, L1-bound    (worse)
//   R12 revert confirm:                 145.8us, DRAM 88.9%
// At the HBM3e write roofline (~7.07 TB/s, 88.5% of spec). This round:
// final knob — 512-thread blocks (completes 128/256/512 sweep).
// Predicted neutral; freeze after this.

constexpr int E_DIM = 2048;
constexpr unsigned NONZERO_E_START = E_DIM - 13;  // 2035

// Total float4 elements: J * E * B / 4 = 2048 * 2048 * 16 = 67,108,864
constexpr unsigned TOTAL_F4 = (unsigned)E_DIM * (unsigned)E_DIM * 16u;
constexpr unsigned QUARTER_F4 = TOTAL_F4 / 4;     // 16,777,216

__device__ __forceinline__ float4 compute_f4(const int* __restrict__ x,
                                             unsigned idx4) {
    // Each (j,e) pair owns B=64 consecutive floats = 16 float4s.
    unsigned pair = idx4 >> 4;            // j * E + e
    unsigned e    = pair & (E_DIM - 1);   // E is a power of two

    float4 val = make_float4(0.f, 0.f, 0.f, 0.f);
    if (e >= NONZERO_E_START) {
        unsigned j = pair >> 11;          // pair / E
        unsigned b = (idx4 & 15u) << 2;   // first of 4 batch lanes
        int shift = (E_DIM - 1) - (int)e; // in [0, 12]
        // x layout: [B, E] row-major -> x[b*E + j]
        int v0 = 2 * __ldg(&x[(b + 0) * E_DIM + j]) + 1;
        int v1 = 2 * __ldg(&x[(b + 1) * E_DIM + j]) + 1;
        int v2 = 2 * __ldg(&x[(b + 2) * E_DIM + j]) + 1;
        int v3 = 2 * __ldg(&x[(b + 3) * E_DIM + j]) + 1;
        val.x = (float)((v0 >> shift) & 1);
        val.y = (float)((v1 >> shift) & 1);
        val.z = (float)((v2 >> shift) & 1);
        val.w = (float)((v3 >> shift) & 1);
    }
    return val;
}

// Streaming store: evict-first, output is dead-on-write (no reuse).
__device__ __forceinline__ void stg_cs_f4(float4* p, float4 v) {
    asm volatile("st.global.cs.v4.f32 [%0], {%1, %2, %3, %4};"
                 :: "l"(p), "f"(v.x), "f"(v.y), "f"(v.z), "f"(v.w)
                 : "memory");
}

__global__ void embedding_bits_kernel(const int* __restrict__ x,
                                      float4* __restrict__ out) {
    unsigned idx4 = blockIdx.x * blockDim.x + threadIdx.x;  // < QUARTER_F4
    // Four independent STG.128.CS per thread. Consecutive lanes hit
    // consecutive 16B -> each warp store is one 512B burst (4 lines).
    float4 a = compute_f4(x, idx4);
    float4 b = compute_f4(x, idx4 + QUARTER_F4);
    float4 c = compute_f4(x, idx4 + 2 * QUARTER_F4);
    float4 d = compute_f4(x, idx4 + 3 * QUARTER_F4);
    stg_cs_f4(&out[idx4], a);
    stg_cs_f4(&out[idx4 + QUARTER_F4], b);
    stg_cs_f4(&out[idx4 + 2 * QUARTER_F4], c);
    stg_cs_f4(&out[idx4 + 3 * QUARTER_F4], d);
}

extern "C" void kernel_launch(void* const* d_in, const int* in_sizes, int n_in,
                              void* d_out, int out_size) {
    const int* x = (const int*)d_in[0];
    float4* out = (float4*)d_out;

    constexpr int THREADS = 512;
    constexpr unsigned BLOCKS = QUARTER_F4 / THREADS;  // 32,768 (exact)
    embedding_bits_kernel<<<BLOCKS, THREADS>>>(x, out);
}